// round 14
// baseline (speedup 1.0000x reference)
#include <cuda_runtime.h>
#include <cuda_fp16.h>
#include <math.h>

// ---------------- constants ----------------
constexpr int B_   = 8;
constexpr int C_   = 2;
constexpr int H_   = 256;
constexpr int W_   = 64;
constexpr int PH_  = 4;
constexpr int PW_  = 4;
constexpr int HP_  = H_ / PH_;   // 64
constexpr int WP_  = W_ / PW_;   // 16
constexpr int N_   = HP_ * WP_;  // 1024
constexpr int HID_ = 1024;
constexpr int NH_  = 16;
constexpr int HD_  = HID_ / NH_; // 64
constexpr int DEPTH_ = 8;
constexpr int FFN_   = 2730;
constexpr int FFNP_  = 2752;
constexpr int NW12_  = 2 * FFNP_; // 5504 interleaved rows
constexpr int TDIM_  = 256;
constexpr int OUT_   = PH_ * PW_ * C_; // 32
constexpr int OUTP_  = 128;
constexpr int T_     = B_ * N_;        // 8192
constexpr float EPS_ = 1e-6f;

typedef unsigned short u16;
typedef unsigned int u32;

// ---------------- scratch (device globals; no allocs) ----------------
__device__ float g_h    [T_ * HID_];
__device__ u16   g_hn   [T_ * HID_];
__device__ u16   g_qkv  [T_ * 3 * HID_];
__device__ float g_q    [T_ * HID_];       // fp32 [B*NH][N][HD]
__device__ u16   g_k    [T_ * HID_];       // fp16 [B*NH][N][HD]
__device__ u16   g_vT   [T_ * HID_];       // fp16 [B*NH][HD][N]
__device__ u16   g_ao   [T_ * HID_];       // fp16 [B][N][NH*HD]
__device__ u16   g_ffn  [T_ * FFNP_];
__device__ float g_fin  [T_ * OUT_];
__device__ float g_cs   [B_ * HID_];
__device__ float g_ada  [DEPTH_ * B_ * 6 * HID_];
__device__ float g_fada [B_ * 2 * HID_];

// fp16 weights (pre-rounded, padded)
__device__ u16 g_wq [DEPTH_ * 3 * HID_ * HID_];
__device__ u16 g_wp [DEPTH_ * HID_ * HID_];
__device__ u16 g_w12[DEPTH_ * NW12_ * HID_];
__device__ u16 g_w3 [DEPTH_ * HID_ * FFNP_];
__device__ u16 g_wf [OUTP_ * HID_];

// ---------------- helpers ----------------
__device__ __forceinline__ void mmah(float* c, const unsigned* a, const unsigned* b) {
    asm volatile("mma.sync.aligned.m16n8k16.row.col.f32.f16.f16.f32 "
                 "{%0,%1,%2,%3},{%4,%5,%6,%7},{%8,%9},{%0,%1,%2,%3};"
                 : "+f"(c[0]), "+f"(c[1]), "+f"(c[2]), "+f"(c[3])
                 : "r"(a[0]), "r"(a[1]), "r"(a[2]), "r"(a[3]), "r"(b[0]), "r"(b[1]));
}
__device__ __forceinline__ void ldm4(unsigned* r, const u16* p) {
    unsigned addr = (unsigned)__cvta_generic_to_shared(p);
    asm volatile("ldmatrix.sync.aligned.m8n8.x4.shared.b16 {%0,%1,%2,%3}, [%4];"
                 : "=r"(r[0]), "=r"(r[1]), "=r"(r[2]), "=r"(r[3]) : "r"(addr));
}
__device__ __forceinline__ void cpa16(u32 dst, const void* src) {
    asm volatile("cp.async.ca.shared.global [%0], [%1], 16;" :: "r"(dst), "l"(src));
}
#define CP_COMMIT asm volatile("cp.async.commit_group;")
#define CP_WAIT2  asm volatile("cp.async.wait_group 2;")
#define CP_WAIT0  asm volatile("cp.async.wait_group 0;")

__device__ __forceinline__ void splith(float v, u16& h, u16& l) {
    __half hb = __float2half_rn(v);
    __half lb = __float2half_rn(v - __half2float(hb));
    h = *reinterpret_cast<u16*>(&hb);
    l = *reinterpret_cast<u16*>(&lb);
}
__device__ __forceinline__ u16 h16(float v) {
    __half hb = __float2half_rn(v);
    return *reinterpret_cast<u16*>(&hb);
}
__device__ __forceinline__ float2 h2f(u32 p) {
    return __half22float2(*reinterpret_cast<__half2*>(&p));
}
__device__ __forceinline__ u32 f2h2(float a, float b) {
    __half2 t = __floats2half2_rn(a, b);
    return *reinterpret_cast<u32*>(&t);
}

// ---------------- fp16 pipelined GEMM (R8 config: 128x128, BK16, 4-stage, occ 2) ----------------
// epilogue modes: 0 fp32(+bias) | 1 fp32 gated residual | 2 swiglu fp16 | 3 fp16(+bias)
constexpr int SROW_ = 24;
constexpr int STG_  = 4;
constexpr int STGB_ = 128 * SROW_ * 2;

__global__ void __launch_bounds__(256, 2)
k_gemm_h1(const u16* __restrict__ A, int lda,
          const u16* __restrict__ W, int ldw,
          void* __restrict__ Cv, int ldc,
          int M, int Nout, int K,
          const float* __restrict__ bias,
          const float* __restrict__ res,
          const float* __restrict__ gate, int gstride, int mode)
{
    __shared__ __align__(16) u16 sA[STG_][128 * SROW_];
    __shared__ __align__(16) u16 sB[STG_][128 * SROW_];

    int n0 = blockIdx.x * 128;
    int m0 = blockIdx.y * 128;
    int tid = threadIdx.x;
    int lane = tid & 31;
    int warp = tid >> 5;
    int wm = warp & 3;
    int wn = warp >> 2;

    int srow = tid >> 1;
    int scol = (tid & 1) * 8;

    const u16* Ap = A + (long long)(m0 + srow) * lda + scol;
    const u16* Wp = W + (long long)(n0 + srow) * ldw + scol;

    u32 baseA = (u32)__cvta_generic_to_shared(&sA[0][0]) + (u32)(srow * SROW_ + scol) * 2;
    u32 baseB = (u32)__cvta_generic_to_shared(&sB[0][0]) + (u32)(srow * SROW_ + scol) * 2;

    int aoff[2], boff[4];
#pragma unroll
    for (int mt = 0; mt < 2; mt++)
        aoff[mt] = (wm * 32 + mt * 16 + (lane & 15)) * SROW_ + ((lane >> 4) * 8);
#pragma unroll
    for (int q = 0; q < 4; q++)
        boff[q] = (wn * 64 + q * 16 + (lane & 7) + ((lane >> 4) << 3)) * SROW_
                + (((lane >> 3) & 1) * 8);

    float acc[2][8][4];
#pragma unroll
    for (int mt = 0; mt < 2; mt++)
#pragma unroll
        for (int nt = 0; nt < 8; nt++)
#pragma unroll
            for (int i = 0; i < 4; i++) acc[mt][nt][i] = 0.0f;

    int ntiles = K / 16;

#define ISSUE(t) do { \
        u32 off_ = (u32)((t) & 3) * STGB_; \
        cpa16(baseA + off_, Ap + (t) * 16); \
        cpa16(baseB + off_, Wp + (t) * 16); \
        CP_COMMIT; \
    } while (0)

    ISSUE(0); ISSUE(1); ISSUE(2);

    for (int t = 0; t < ntiles; t++) {
        CP_WAIT2;
        __syncthreads();
        if (t + 3 < ntiles) ISSUE(t + 3);
        int buf = t & 3;

        unsigned af[2][4];
        unsigned bf[8][2];
#pragma unroll
        for (int mt = 0; mt < 2; mt++)
            ldm4(af[mt], &sA[buf][aoff[mt]]);
#pragma unroll
        for (int q = 0; q < 4; q++) {
            unsigned r[4];
            ldm4(r, &sB[buf][boff[q]]);
            bf[2*q][0] = r[0]; bf[2*q][1] = r[1];
            bf[2*q+1][0] = r[2]; bf[2*q+1][1] = r[3];
        }
#pragma unroll
        for (int mt = 0; mt < 2; mt++)
#pragma unroll
            for (int nt = 0; nt < 8; nt++)
                mmah(acc[mt][nt], af[mt], bf[nt]);
    }
#undef ISSUE

    // ---- epilogue ----
#pragma unroll
    for (int mt = 0; mt < 2; mt++) {
        int row = m0 + wm * 32 + mt * 16 + (lane >> 2);
#pragma unroll
        for (int nt = 0; nt < 8; nt++) {
            int col = n0 + wn * 64 + nt * 8 + ((lane & 3) << 1);
#pragma unroll
            for (int half = 0; half < 2; half++) {
                int m = row + half * 8;
                float a0 = acc[mt][nt][half * 2 + 0];
                float a1 = acc[mt][nt][half * 2 + 1];
                if (mode == 2) {
                    int j = col >> 1;
                    float b1 = 0.0f, b2 = 0.0f;
                    if (j < FFN_) { b1 = __ldg(bias + j); b2 = __ldg(bias + FFN_ + j); }
                    float x1 = a0 + b1, x2 = a1 + b2;
                    float r = x1 / (1.0f + __expf(-x1)) * x2;
                    ((u16*)Cv)[(long long)m * FFNP_ + j] = h16(r);
                } else if (mode == 3) {
                    if (col < Nout) {
                        float v0 = a0 + __ldg(bias + col);
                        float v1 = a1 + __ldg(bias + col + 1);
                        *reinterpret_cast<u32*>((u16*)Cv + (long long)m * ldc + col) = f2h2(v0, v1);
                    }
                } else {
                    float* C = (float*)Cv;
#pragma unroll
                    for (int e = 0; e < 2; e++) {
                        int nn = col + e;
                        if (nn < Nout) {
                            float v = (e == 0) ? a0 : a1;
                            if (bias) v += __ldg(bias + nn);
                            long long idx = (long long)m * ldc + nn;
                            if (mode == 1)
                                v = res[idx] + gate[(m >> 10) * gstride + nn] * v;
                            C[idx] = v;
                        }
                    }
                }
            }
        }
    }
}

// ---------------- fast weight conversion: one block per dst row ----------------
__global__ void k_wcvt_row(const float* __restrict__ src, u16* __restrict__ dst,
                           int srcK, int dstK, int srcRows, int dstRows)
{
    int r = blockIdx.x;
    int mat = r / dstRows;
    int rr = r - mat * dstRows;
    const float* s = src + ((long long)mat * srcRows + rr) * srcK;
    u16* d = dst + (long long)r * dstK;
    bool valid = rr < srcRows;
    for (int j = threadIdx.x * 2; j < dstK; j += 512) {
        float v0 = (valid && j < srcK) ? s[j] : 0.0f;
        float v1 = (valid && j + 1 < srcK) ? s[j + 1] : 0.0f;
        *reinterpret_cast<u32*>(d + j) = f2h2(v0, v1);
    }
}

__global__ void k_wcvt12_row(const float* __restrict__ src, u16* __restrict__ dst)
{
    int r = blockIdx.x;
    int dd = r / NW12_;
    int r2 = r - dd * NW12_;
    int pj = r2 >> 1;
    int hf = r2 & 1;
    u16* d = dst + (long long)r * HID_;
    if (pj >= FFN_) {
        for (int j = threadIdx.x * 2; j < HID_; j += 512)
            *reinterpret_cast<u32*>(d + j) = 0u;
        return;
    }
    const float* s = src + ((long long)dd * 2 * FFN_ + hf * FFN_ + pj) * HID_;
    for (int j = threadIdx.x * 2; j < HID_; j += 512) {
        float2 v = *reinterpret_cast<const float2*>(s + j);
        *reinterpret_cast<u32*>(d + j) = f2h2(v.x, v.y);
    }
}

// ---------------- FA2-style flash attention: register P, warp = 16 q-rows x 64 keys ----------------
constexpr int FST = 72;                   // u16 row stride
constexpr int FQH = 0;
constexpr int FQL = FQH + 128 * FST;
constexpr int FK0 = FQL + 128 * FST;      // K double buffer [2][64*FST]
constexpr int FV0 = FK0 + 2 * 64 * FST;   // V double buffer [2][64*FST]
constexpr int F_TOT = FV0 + 2 * 64 * FST;
constexpr int FLASH_SMEM = F_TOT * 2;     // 73728 bytes
constexpr int KVSTRIDE = 64 * FST;        // u16 per K/V buffer

__global__ void __launch_bounds__(256, 2)
k_flash(const float* __restrict__ gq, const u16* __restrict__ gk,
        const u16* __restrict__ gvT, u16* __restrict__ gao)
{
    extern __shared__ __align__(16) u16 su[];
    u16* sQh = su + FQH;
    u16* sQl = su + FQL;
    u16* sK  = su + FK0;
    u16* sV  = su + FV0;

    int tid = threadIdx.x;
    int lane = tid & 31;
    int warp = tid >> 5;            // 0..7, owns q rows warp*16..+15

    int bh = blockIdx.y;
    int q0 = blockIdx.x * 128;
    const float* Qg = gq + ((long long)bh * N_ + q0) * HD_;
    const u16* Kg = gk + (long long)bh * N_ * HD_;
    const u16* Vg = gvT + (long long)bh * HD_ * N_;

    // load Q (x 0.125), split fp16 hi/lo
    {
        int r = tid >> 1, c0 = (tid & 1) * 32;
#pragma unroll
        for (int i = 0; i < 8; i++) {
            float4 v = *reinterpret_cast<const float4*>(Qg + (long long)r * HD_ + c0 + i * 4);
            v.x *= 0.125f; v.y *= 0.125f; v.z *= 0.125f; v.w *= 0.125f;
            u16 h[4], l[4];
            splith(v.x, h[0], l[0]); splith(v.y, h[1], l[1]);
            splith(v.z, h[2], l[2]); splith(v.w, h[3], l[3]);
            *reinterpret_cast<uint2*>(&sQh[r * FST + c0 + i * 4]) = *reinterpret_cast<uint2*>(h);
            *reinterpret_cast<uint2*>(&sQl[r * FST + c0 + i * 4]) = *reinterpret_cast<uint2*>(l);
        }
    }

    // cp.async K/V loader mapping
    int kr = tid >> 2, kc = (tid & 3) * 16;
    u32 kdst = (u32)__cvta_generic_to_shared(sK) + (u32)(kr * FST + kc) * 2;
    u32 vdst = (u32)__cvta_generic_to_shared(sV) + (u32)(kr * FST + kc) * 2;

#define KVISSUE(cc) do { \
        u32 off_ = (u32)((cc) & 1) * (KVSTRIDE * 2); \
        const u16* ks_ = Kg + ((long long)(cc) * 64 + kr) * HD_ + kc; \
        const u16* vs_ = Vg + (long long)kr * N_ + (long long)(cc) * 64 + kc; \
        cpa16(kdst + off_, ks_); cpa16(kdst + off_ + 16, ks_ + 8); \
        cpa16(vdst + off_, vs_); cpa16(vdst + off_ + 16, vs_ + 8); \
        CP_COMMIT; \
    } while (0)

    KVISSUE(0);

    // fragment offsets
    int aoffQ = (warp * 16 + (lane & 15)) * FST + ((lane >> 4) * 8);
    int nboff[4];
#pragma unroll
    for (int g = 0; g < 4; g++)
        nboff[g] = (g * 16 + (lane & 7) + ((lane >> 4) << 3)) * FST + (((lane >> 3) & 1) * 8);

    float m_st[2] = { -1e30f, -1e30f };
    float l_st[2] = { 0.0f, 0.0f };
    float o[8][4];
#pragma unroll
    for (int nt = 0; nt < 8; nt++)
#pragma unroll
        for (int i = 0; i < 4; i++) o[nt][i] = 0.0f;

    for (int c = 0; c < 16; c++) {
        CP_WAIT0;
        __syncthreads();
        if (c < 15) KVISSUE(c + 1);
        const u16* bK = sK + (c & 1) * KVSTRIDE;
        const u16* bV = sV + (c & 1) * KVSTRIDE;

        // MMA1: S[16 q x 64 keys] = (Qh + Ql) @ K^T
        float s[8][4];
#pragma unroll
        for (int nt = 0; nt < 8; nt++)
#pragma unroll
            for (int i = 0; i < 4; i++) s[nt][i] = 0.0f;
#pragma unroll
        for (int ks = 0; ks < 4; ks++) {
            unsigned ah[4], al[4], bk[8][2];
            ldm4(ah, &sQh[aoffQ + ks * 16]);
            ldm4(al, &sQl[aoffQ + ks * 16]);
#pragma unroll
            for (int g = 0; g < 4; g++) {
                unsigned r[4];
                ldm4(r, bK + nboff[g] + ks * 16);
                bk[2*g][0] = r[0]; bk[2*g][1] = r[1];
                bk[2*g+1][0] = r[2]; bk[2*g+1][1] = r[3];
            }
#pragma unroll
            for (int nt = 0; nt < 8; nt++) {
                mmah(s[nt], ah, bk[nt]);
                mmah(s[nt], al, bk[nt]);
            }
        }

        // warp-local online softmax (rows: h=0 -> lane>>2, h=1 -> +8)
#pragma unroll
        for (int h = 0; h < 2; h++) {
            float mx = m_st[h];
#pragma unroll
            for (int nt = 0; nt < 8; nt++)
                mx = fmaxf(mx, fmaxf(s[nt][2*h], s[nt][2*h+1]));
            mx = fmaxf(mx, __shfl_xor_sync(0xffffffffu, mx, 1));
            mx = fmaxf(mx, __shfl_xor_sync(0xffffffffu, mx, 2));
            float corr = __expf(m_st[h] - mx);
            float sum = 0.0f;
#pragma unroll
            for (int nt = 0; nt < 8; nt++) {
                float p0 = __expf(s[nt][2*h] - mx);
                float p1 = __expf(s[nt][2*h+1] - mx);
                sum += p0 + p1;
                s[nt][2*h] = p0; s[nt][2*h+1] = p1;
            }
            sum += __shfl_xor_sync(0xffffffffu, sum, 1);
            sum += __shfl_xor_sync(0xffffffffu, sum, 2);
            l_st[h] = l_st[h] * corr + sum;
            m_st[h] = mx;
#pragma unroll
            for (int nt = 0; nt < 8; nt++) {
                o[nt][2*h] *= corr; o[nt][2*h+1] *= corr;
            }
        }

        // pack P (register) into A fragments: kb over 4 k16 blocks
        unsigned ap[4][4];
#pragma unroll
        for (int kb = 0; kb < 4; kb++) {
            ap[kb][0] = f2h2(s[2*kb][0],   s[2*kb][1]);
            ap[kb][1] = f2h2(s[2*kb][2],   s[2*kb][3]);
            ap[kb][2] = f2h2(s[2*kb+1][0], s[2*kb+1][1]);
            ap[kb][3] = f2h2(s[2*kb+1][2], s[2*kb+1][3]);
        }

        // MMA2: O[16 q x 64 d] += P @ V^T
#pragma unroll
        for (int kb = 0; kb < 4; kb++) {
            unsigned bv[8][2];
#pragma unroll
            for (int dg = 0; dg < 4; dg++) {
                unsigned r[4];
                ldm4(r, bV + nboff[dg] + kb * 16);
                bv[2*dg][0] = r[0]; bv[2*dg][1] = r[1];
                bv[2*dg+1][0] = r[2]; bv[2*dg+1][1] = r[3];
            }
#pragma unroll
            for (int nt = 0; nt < 8; nt++)
                mmah(o[nt], ap[kb], bv[nt]);
        }
    }
#undef KVISSUE

    // output: scatter into (B, N, NH, HD), scaled by 1/l
    float inv0 = 1.0f / l_st[0];
    float inv1 = 1.0f / l_st[1];
    int bb = bh >> 4, hh = bh & 15;
    int r0 = q0 + warp * 16 + (lane >> 2);
#pragma unroll
    for (int nt = 0; nt < 8; nt++) {
        int col = nt * 8 + (lane & 3) * 2;
        long long a0 = ((long long)(bb * N_ + r0) * NH_ + hh) * HD_ + col;
        long long a1 = ((long long)(bb * N_ + r0 + 8) * NH_ + hh) * HD_ + col;
        *reinterpret_cast<u32*>(gao + a0) = f2h2(o[nt][0] * inv0, o[nt][1] * inv0);
        *reinterpret_cast<u32*>(gao + a1) = f2h2(o[nt][2] * inv1, o[nt][3] * inv1);
    }
}

// ---------------- timestep embedding -> c -> silu(c) ----------------
__global__ void k_timestep(const float* __restrict__ t,
                           const float* __restrict__ t_w,
                           const float* __restrict__ t_b)
{
    int b = blockIdx.x;
    int tid = threadIdx.x;
    __shared__ float te[TDIM_];
    float tv = t[b];
    {
        int j = tid & 127;
        float f = __expf(-logf(10000.0f) * (float)j / 128.0f);
        float a = tv * f;
        te[tid] = (tid < 128) ? cosf(a) : sinf(a);
    }
    __syncthreads();
#pragma unroll
    for (int rep = 0; rep < 4; rep++) {
        int o = tid + rep * 256;
        float acc = t_b[o];
        const float* w = t_w + (long long)o * TDIM_;
        for (int j = 0; j < TDIM_; j += 4) {
            float4 wv = *reinterpret_cast<const float4*>(w + j);
            acc += te[j] * wv.x + te[j+1] * wv.y + te[j+2] * wv.z + te[j+3] * wv.w;
        }
        float sig = 1.0f / (1.0f + __expf(-acc));
        g_cs[b * HID_ + o] = acc * sig;
    }
}

// ---------------- all adaLN projections ----------------
__global__ void k_ada(const float* __restrict__ ada_w,
                      const float* __restrict__ ada_b,
                      const float* __restrict__ fada_w,
                      const float* __restrict__ fada_b)
{
    int d = blockIdx.x;
    int chunk = blockIdx.y;
    int tid = threadIdx.x;
    __shared__ float css[B_][HID_];
    for (int i = tid; i < B_ * HID_; i += 256)
        css[i >> 10][i & 1023] = g_cs[i];
    __syncthreads();

    int cnt = (d < DEPTH_) ? 6 * HID_ : 2 * HID_;
    int o = chunk * 256 + tid;
    if (o >= cnt) return;

    const float* W = (d < DEPTH_) ? ada_w + ((long long)d * 6 * HID_ + o) * HID_
                                  : fada_w + (long long)o * HID_;
    float bia = (d < DEPTH_) ? ada_b[d * 6 * HID_ + o] : fada_b[o];
    float acc[B_];
#pragma unroll
    for (int b = 0; b < B_; b++) acc[b] = bia;

    for (int j = 0; j < HID_; j += 4) {
        float4 wv = *reinterpret_cast<const float4*>(W + j);
#pragma unroll
        for (int b = 0; b < B_; b++) {
            acc[b] += css[b][j] * wv.x + css[b][j+1] * wv.y
                    + css[b][j+2] * wv.z + css[b][j+3] * wv.w;
        }
    }
#pragma unroll
    for (int b = 0; b < B_; b++) {
        if (d < DEPTH_) g_ada[((long long)(d * B_ + b)) * 6 * HID_ + o] = acc[b];
        else            g_fada[b * 2 * HID_ + o] = acc[b];
    }
}

// ---------------- patchify + bias + pos embed ----------------
__global__ void k_patch(const float* __restrict__ x,
                        const float* __restrict__ patch_w,
                        const float* __restrict__ patch_b)
{
    int tok = blockIdx.x;
    int b = tok >> 10;
    int n = tok & 1023;
    int hp = n >> 4;
    int wp = n & 15;
    int tid = threadIdx.x;
    __shared__ float xs[32];
    if (tid < 32) {
        int c = tid >> 4;
        int r = (tid >> 2) & 3;
        int q = tid & 3;
        xs[c * 16 + r * 4 + q] = x[((long long)(b * C_ + c) * H_ + hp * 4 + r) * W_ + wp * 4 + q];
    }
    __syncthreads();
    const float LOG1E4 = logf(10000.0f);
#pragma unroll
    for (int rep = 0; rep < 4; rep++) {
        int o = tid + rep * 256;
        float acc = patch_b[o];
        const float4* w4 = reinterpret_cast<const float4*>(patch_w + o * 32);
#pragma unroll
        for (int i = 0; i < 8; i++) {
            float4 wv = w4[i];
            acc += xs[i*4+0] * wv.x + xs[i*4+1] * wv.y + xs[i*4+2] * wv.z + xs[i*4+3] * wv.w;
        }
        int j = o & 255;
        int sec = o >> 8;
        float omega = __expf(-LOG1E4 * (float)j / 256.0f);
        float p = (sec < 2) ? (float)wp : (float)hp;
        float a = p * omega;
        float pos = (sec & 1) ? cosf(a) : sinf(a);
        g_h[(long long)tok * HID_ + o] = acc + pos;
    }
}

// ---------------- RMSNorm + modulate -> fp16 (warp-shuffle reduction, 1 barrier) ----------------
__global__ void k_rmsmod(const float* __restrict__ in, u16* __restrict__ out,
                         const float* __restrict__ nw,
                         const float* __restrict__ ada, int ada_stride,
                         int shift_off, int scale_off)
{
    int tok = blockIdx.x;
    int b = tok >> 10;
    int tid = threadIdx.x;
    const float* row = in + (long long)tok * HID_;
    float v[4];
    float s = 0.0f;
#pragma unroll
    for (int i = 0; i < 4; i++) { v[i] = row[tid + i * 256]; s += v[i] * v[i]; }
#pragma unroll
    for (int o = 16; o > 0; o >>= 1) s += __shfl_xor_sync(0xffffffffu, s, o);
    __shared__ float ws[8];
    if ((tid & 31) == 0) ws[tid >> 5] = s;
    __syncthreads();
    float tot = (ws[0] + ws[1]) + (ws[2] + ws[3]) + (ws[4] + ws[5]) + (ws[6] + ws[7]);
    float rs = rsqrtf(tot / (float)HID_ + EPS_);
    const float* ar = ada + (long long)b * ada_stride;
    u16* orow = out + (long long)tok * HID_;
#pragma unroll
    for (int i = 0; i < 4; i++) {
        int cidx = tid + i * 256;
        orow[cidx] = h16(v[i] * rs * nw[cidx] * (1.0f + ar[scale_off + cidx]) + ar[shift_off + cidx]);
    }
}

// ---------------- per-head qk RMSNorm + RoPE + v transpose (fp16 in) ----------------
__global__ void k_rope(const float* __restrict__ qn, const float* __restrict__ kn)
{
    int tok = blockIdx.x;
    int b = tok >> 10;
    int n = tok & 1023;
    int tid = threadIdx.x;
    int h = tid >> 4;
    int l = tid & 15;
    int d0 = l * 4;
    const u16* row = g_qkv + (long long)tok * 3 * HID_;
    uint2 qr = *reinterpret_cast<const uint2*>(row + h * HD_ + d0);
    uint2 kr = *reinterpret_cast<const uint2*>(row + HID_ + h * HD_ + d0);
    uint2 vr = *reinterpret_cast<const uint2*>(row + 2 * HID_ + h * HD_ + d0);
    float2 q01 = h2f(qr.x), q23 = h2f(qr.y);
    float2 k01 = h2f(kr.x), k23 = h2f(kr.y);
    float4 q = make_float4(q01.x, q01.y, q23.x, q23.y);
    float4 k = make_float4(k01.x, k01.y, k23.x, k23.y);

    float sq = q.x*q.x + q.y*q.y + q.z*q.z + q.w*q.w;
    float sk = k.x*k.x + k.y*k.y + k.z*k.z + k.w*k.w;
#pragma unroll
    for (int o = 1; o < 16; o <<= 1) {
        sq += __shfl_xor_sync(0xffffffffu, sq, o);
        sk += __shfl_xor_sync(0xffffffffu, sk, o);
    }
    float rq = rsqrtf(sq / (float)HD_ + EPS_);
    float rk = rsqrtf(sk / (float)HD_ + EPS_);
    q.x *= rq * qn[d0+0]; q.y *= rq * qn[d0+1]; q.z *= rq * qn[d0+2]; q.w *= rq * qn[d0+3];
    k.x *= rk * kn[d0+0]; k.y *= rk * kn[d0+1]; k.z *= rk * kn[d0+2]; k.w *= rk * kn[d0+3];

    const float LOG1E4 = logf(10000.0f);
    float hpos = (float)(n >> 4);
    float wpos = (float)(n & 15);
#pragma unroll
    for (int pr = 0; pr < 2; pr++) {
        int dp = d0 + pr * 2;
        int jj; float pos;
        if (dp < 32) { jj = dp;      pos = hpos; }
        else         { jj = dp - 32; pos = wpos; }
        float freq = __expf(-LOG1E4 * (float)jj / 32.0f);
        float ang = pos * freq;
        float c = cosf(ang), s = sinf(ang);
        float qx0 = (pr == 0) ? q.x : q.z;
        float qx1 = (pr == 0) ? q.y : q.w;
        float kx0 = (pr == 0) ? k.x : k.z;
        float kx1 = (pr == 0) ? k.y : k.w;
        float qy0 = qx0 * c - qx1 * s;
        float qy1 = qx1 * c + qx0 * s;
        float ky0 = kx0 * c - kx1 * s;
        float ky1 = kx1 * c + kx0 * s;
        if (pr == 0) { q.x = qy0; q.y = qy1; k.x = ky0; k.y = ky1; }
        else         { q.z = qy0; q.w = qy1; k.z = ky0; k.w = ky1; }
    }

    long long qbase = ((long long)(b * NH_ + h) * N_ + n) * HD_ + d0;
    *reinterpret_cast<float4*>(g_q + qbase) = q;
    uint2 kp; kp.x = f2h2(k.x, k.y); kp.y = f2h2(k.z, k.w);
    *reinterpret_cast<uint2*>(g_k + qbase) = kp;
    long long vb = (long long)(b * NH_ + h) * HD_;
    g_vT[(vb + d0 + 0) * N_ + n] = (u16)(vr.x & 0xffff);
    g_vT[(vb + d0 + 1) * N_ + n] = (u16)(vr.x >> 16);
    g_vT[(vb + d0 + 2) * N_ + n] = (u16)(vr.y & 0xffff);
    g_vT[(vb + d0 + 3) * N_ + n] = (u16)(vr.y >> 16);
}

// ---------------- unpatchify ----------------
__global__ void k_unpatch(float* __restrict__ out)
{
    int idx = blockIdx.x * 256 + threadIdx.x;
    if (idx >= B_ * C_ * H_ * W_) return;
    int ww = idx % W_;
    int tmp = idx / W_;
    int hh = tmp % H_;
    int tmp2 = tmp / H_;
    int c = tmp2 % C_;
    int b = tmp2 / C_;
    int hp = hh >> 2, p = hh & 3;
    int wp = ww >> 2, q = ww & 3;
    out[idx] = g_fin[((long long)(b * N_ + hp * WP_ + wp)) * OUT_ + p * (PW_ * C_) + q * C_ + c];
}

// ---------------- host orchestration ----------------
extern "C" void kernel_launch(void* const* d_in, const int* in_sizes, int n_in,
                              void* d_out, int out_size)
{
    const float* x       = (const float*)d_in[0];
    const float* t       = (const float*)d_in[1];
    const float* patch_w = (const float*)d_in[2];
    const float* patch_b = (const float*)d_in[3];
    const float* t_w     = (const float*)d_in[4];
    const float* t_b     = (const float*)d_in[5];
    const float* norm1_w = (const float*)d_in[6];
    const float* qkv_w   = (const float*)d_in[7];
    const float* qkv_b   = (const float*)d_in[8];
    const float* qn_w    = (const float*)d_in[9];
    const float* kn_w    = (const float*)d_in[10];
    const float* proj_w  = (const float*)d_in[11];
    const float* proj_b  = (const float*)d_in[12];
    const float* norm2_w = (const float*)d_in[13];
    const float* w12_w   = (const float*)d_in[14];
    const float* w12_b   = (const float*)d_in[15];
    const float* w3_w    = (const float*)d_in[16];
    const float* w3_b    = (const float*)d_in[17];
    const float* ada_w   = (const float*)d_in[18];
    const float* ada_b   = (const float*)d_in[19];
    const float* fnorm_w = (const float*)d_in[20];
    const float* flin_w  = (const float*)d_in[21];
    const float* flin_b  = (const float*)d_in[22];
    const float* fada_w  = (const float*)d_in[23];
    const float* fada_b  = (const float*)d_in[24];
    float* out = (float*)d_out;

    cudaFuncSetAttribute(k_flash, cudaFuncAttributeMaxDynamicSharedMemorySize, FLASH_SMEM);

    float *p_h, *p_q, *p_fin, *p_ada, *p_fada;
    u16 *p_hn, *p_qkv, *p_k, *p_vT, *p_ao, *p_ffn, *p_wq, *p_wp, *p_w12, *p_w3, *p_wf;
    cudaGetSymbolAddress((void**)&p_h,   g_h);
    cudaGetSymbolAddress((void**)&p_hn,  g_hn);
    cudaGetSymbolAddress((void**)&p_qkv, g_qkv);
    cudaGetSymbolAddress((void**)&p_q,   g_q);
    cudaGetSymbolAddress((void**)&p_k,   g_k);
    cudaGetSymbolAddress((void**)&p_vT,  g_vT);
    cudaGetSymbolAddress((void**)&p_ao,  g_ao);
    cudaGetSymbolAddress((void**)&p_ffn, g_ffn);
    cudaGetSymbolAddress((void**)&p_fin, g_fin);
    cudaGetSymbolAddress((void**)&p_ada, g_ada);
    cudaGetSymbolAddress((void**)&p_fada, g_fada);
    cudaGetSymbolAddress((void**)&p_wq,  g_wq);
    cudaGetSymbolAddress((void**)&p_wp,  g_wp);
    cudaGetSymbolAddress((void**)&p_w12, g_w12);
    cudaGetSymbolAddress((void**)&p_w3,  g_w3);
    cudaGetSymbolAddress((void**)&p_wf,  g_wf);

    auto cvt = [](const float* src, u16* dst, int srcK, int dstK,
                  int srcRows, int dstRows, int mats) {
        k_wcvt_row<<<mats * dstRows, 256>>>(src, dst, srcK, dstK, srcRows, dstRows);
    };

    auto gemm = [](const u16* A, int lda, const u16* Wh, int ldw,
                   void* C, int ldc, int M, int Nout, int K,
                   const float* bias, const float* res,
                   const float* gate, int gstride, int mode) {
        dim3 grid((Nout + 127) / 128, M / 128);
        k_gemm_h1<<<grid, 256>>>(A, lda, Wh, ldw, C, ldc, M, Nout, K,
                                 bias, res, gate, gstride, mode);
    };

    // setup
    k_timestep<<<B_, 256>>>(t, t_w, t_b);
    k_ada<<<dim3(DEPTH_ + 1, 24), 256>>>(ada_w, ada_b, fada_w, fada_b);
    cvt(qkv_w, p_wq, HID_, HID_, 3 * HID_, 3 * HID_, DEPTH_);
    cvt(proj_w, p_wp, HID_, HID_, HID_, HID_, DEPTH_);
    k_wcvt12_row<<<DEPTH_ * NW12_, 256>>>(w12_w, p_w12);
    cvt(w3_w, p_w3, FFN_, FFNP_, HID_, HID_, DEPTH_);
    cvt(flin_w, p_wf, HID_, HID_, OUT_, OUTP_, 1);
    k_patch<<<T_, 256>>>(x, patch_w, patch_b);

    for (int d = 0; d < DEPTH_; d++) {
        const float* adab = p_ada + (long long)d * B_ * 6 * HID_;

        // norm1 + modulate -> fp16
        k_rmsmod<<<T_, 256>>>(p_h, p_hn, norm1_w + d * HID_, adab, 6 * HID_, 0, HID_);

        // qkv -> fp16
        gemm(p_hn, HID_, p_wq + (long long)d * 3 * HID_ * HID_, HID_,
             p_qkv, 3 * HID_, T_, 3 * HID_, HID_,
             qkv_b + d * 3 * HID_, nullptr, nullptr, 0, 3);

        // qk-norm + rope + v transpose
        k_rope<<<T_, 256>>>(qn_w + d * HD_, kn_w + d * HD_);

        // fused flash attention -> g_ao (fp16)
        k_flash<<<dim3(N_ / 128, B_ * NH_), 256, FLASH_SMEM>>>(p_q, p_k, p_vT, p_ao);

        // proj + gated residual (gm)
        gemm(p_ao, HID_, p_wp + (long long)d * HID_ * HID_, HID_,
             p_h, HID_, T_, HID_, HID_,
             proj_b + d * HID_, p_h, adab + 2 * HID_, 6 * HID_, 1);

        // norm2 + modulate -> fp16
        k_rmsmod<<<T_, 256>>>(p_h, p_hn, norm2_w + d * HID_, adab, 6 * HID_, 3 * HID_, 4 * HID_);

        // w12 GEMM with fused swiglu -> g_ffn (fp16)
        gemm(p_hn, HID_, p_w12 + (long long)d * NW12_ * HID_, HID_,
             p_ffn, FFNP_, T_, NW12_, HID_,
             w12_b + (long long)d * 2 * FFN_, nullptr, nullptr, 0, 2);

        // w3 + gated residual (gp)
        gemm(p_ffn, FFNP_, p_w3 + (long long)d * HID_ * FFNP_, FFNP_,
             p_h, HID_, T_, HID_, FFNP_,
             w3_b + d * HID_, p_h, adab + 5 * HID_, 6 * HID_, 1);
    }

    // final norm + modulate -> fp16
    k_rmsmod<<<T_, 256>>>(p_h, p_hn, fnorm_w, p_fada, 2 * HID_, 0, HID_);

    // final linear
    gemm(p_hn, HID_, p_wf, HID_,
         p_fin, OUT_, T_, OUT_, HID_,
         flin_b, nullptr, nullptr, 0, 0);

    k_unpatch<<<(B_ * C_ * H_ * W_ + 255) / 256, 256>>>(out);
}

// round 17
// speedup vs baseline: 1.0602x; 1.0602x over previous
#include <cuda_runtime.h>
#include <cuda_fp16.h>
#include <math.h>

// ---------------- constants ----------------
constexpr int B_   = 8;
constexpr int C_   = 2;
constexpr int H_   = 256;
constexpr int W_   = 64;
constexpr int PH_  = 4;
constexpr int PW_  = 4;
constexpr int HP_  = H_ / PH_;   // 64
constexpr int WP_  = W_ / PW_;   // 16
constexpr int N_   = HP_ * WP_;  // 1024
constexpr int HID_ = 1024;
constexpr int NH_  = 16;
constexpr int HD_  = HID_ / NH_; // 64
constexpr int DEPTH_ = 8;
constexpr int FFN_   = 2730;
constexpr int FFNP_  = 2752;
constexpr int NW12_  = 2 * FFNP_; // 5504 interleaved rows
constexpr int TDIM_  = 256;
constexpr int OUT_   = PH_ * PW_ * C_; // 32
constexpr int OUTP_  = 128;
constexpr int T_     = B_ * N_;        // 8192
constexpr float EPS_ = 1e-6f;

typedef unsigned short u16;
typedef unsigned int u32;

// ---------------- scratch (device globals; no allocs) ----------------
__device__ float g_h    [T_ * HID_];
__device__ u16   g_hn   [T_ * HID_];
__device__ u16   g_qkv  [T_ * 3 * HID_];
__device__ float g_q    [T_ * HID_];       // fp32 [B*NH][N][HD]
__device__ u16   g_k    [T_ * HID_];       // fp16 [B*NH][N][HD]
__device__ u16   g_vT   [T_ * HID_];       // fp16 [B*NH][HD][N]
__device__ u16   g_ao   [T_ * HID_];       // fp16 [B][N][NH*HD]
__device__ u16   g_ffn  [T_ * FFNP_];
__device__ float g_fin  [T_ * OUT_];
__device__ float g_cs   [B_ * HID_];
__device__ float g_ada  [DEPTH_ * B_ * 6 * HID_];
__device__ float g_fada [B_ * 2 * HID_];

// fp16 weights (pre-rounded, padded)
__device__ u16 g_wq [DEPTH_ * 3 * HID_ * HID_];
__device__ u16 g_wp [DEPTH_ * HID_ * HID_];
__device__ u16 g_w12[DEPTH_ * NW12_ * HID_];
__device__ u16 g_w3 [DEPTH_ * HID_ * FFNP_];
__device__ u16 g_wf [OUTP_ * HID_];

// ---------------- helpers ----------------
__device__ __forceinline__ void mmah(float* c, const unsigned* a, const unsigned* b) {
    asm volatile("mma.sync.aligned.m16n8k16.row.col.f32.f16.f16.f32 "
                 "{%0,%1,%2,%3},{%4,%5,%6,%7},{%8,%9},{%0,%1,%2,%3};"
                 : "+f"(c[0]), "+f"(c[1]), "+f"(c[2]), "+f"(c[3])
                 : "r"(a[0]), "r"(a[1]), "r"(a[2]), "r"(a[3]), "r"(b[0]), "r"(b[1]));
}
__device__ __forceinline__ void ldm4(unsigned* r, const u16* p) {
    unsigned addr = (unsigned)__cvta_generic_to_shared(p);
    asm volatile("ldmatrix.sync.aligned.m8n8.x4.shared.b16 {%0,%1,%2,%3}, [%4];"
                 : "=r"(r[0]), "=r"(r[1]), "=r"(r[2]), "=r"(r[3]) : "r"(addr));
}
__device__ __forceinline__ void cpa16(u32 dst, const void* src) {
    asm volatile("cp.async.ca.shared.global [%0], [%1], 16;" :: "r"(dst), "l"(src));
}
#define CP_COMMIT asm volatile("cp.async.commit_group;")
#define CP_WAIT2  asm volatile("cp.async.wait_group 2;")
#define CP_WAIT0  asm volatile("cp.async.wait_group 0;")

__device__ __forceinline__ void splith(float v, u16& h, u16& l) {
    __half hb = __float2half_rn(v);
    __half lb = __float2half_rn(v - __half2float(hb));
    h = *reinterpret_cast<u16*>(&hb);
    l = *reinterpret_cast<u16*>(&lb);
}
__device__ __forceinline__ u16 h16(float v) {
    __half hb = __float2half_rn(v);
    return *reinterpret_cast<u16*>(&hb);
}
__device__ __forceinline__ float2 h2f(u32 p) {
    return __half22float2(*reinterpret_cast<__half2*>(&p));
}
__device__ __forceinline__ u32 f2h2(float a, float b) {
    __half2 t = __floats2half2_rn(a, b);
    return *reinterpret_cast<u32*>(&t);
}

// ---------------- fp16 pipelined GEMM (128x128, BK16, 4-stage, occ 2) ----------------
// MODE: 0 fp32 out (+bias, bounds-checked) | 1 fp32 gated residual (full tiles)
//       2 swiglu fp16 (interleaved w12)    | 3 fp16 out (+bias, full tiles)
constexpr int SROW_ = 24;
constexpr int STG_  = 4;
constexpr int STGB_ = 128 * SROW_ * 2;

template <int MODE>
__global__ void __launch_bounds__(256, 2)
k_gemm_h1(const u16* __restrict__ A, int lda,
          const u16* __restrict__ W, int ldw,
          void* __restrict__ Cv, int ldc,
          int M, int Nout, int K,
          const float* __restrict__ bias,
          const float* __restrict__ res,
          const float* __restrict__ gate, int gstride)
{
    __shared__ __align__(16) u16 sA[STG_][128 * SROW_];
    __shared__ __align__(16) u16 sB[STG_][128 * SROW_];

    int n0 = blockIdx.x * 128;
    int m0 = blockIdx.y * 128;
    int tid = threadIdx.x;
    int lane = tid & 31;
    int warp = tid >> 5;
    int wm = warp & 3;
    int wn = warp >> 2;

    int srow = tid >> 1;
    int scol = (tid & 1) * 8;

    const u16* Ap = A + (long long)(m0 + srow) * lda + scol;
    const u16* Wp = W + (long long)(n0 + srow) * ldw + scol;

    u32 baseA = (u32)__cvta_generic_to_shared(&sA[0][0]) + (u32)(srow * SROW_ + scol) * 2;
    u32 baseB = (u32)__cvta_generic_to_shared(&sB[0][0]) + (u32)(srow * SROW_ + scol) * 2;

    int aoff[2], boff[4];
#pragma unroll
    for (int mt = 0; mt < 2; mt++)
        aoff[mt] = (wm * 32 + mt * 16 + (lane & 15)) * SROW_ + ((lane >> 4) * 8);
#pragma unroll
    for (int q = 0; q < 4; q++)
        boff[q] = (wn * 64 + q * 16 + (lane & 7) + ((lane >> 4) << 3)) * SROW_
                + (((lane >> 3) & 1) * 8);

    float acc[2][8][4];
#pragma unroll
    for (int mt = 0; mt < 2; mt++)
#pragma unroll
        for (int nt = 0; nt < 8; nt++)
#pragma unroll
            for (int i = 0; i < 4; i++) acc[mt][nt][i] = 0.0f;

    int ntiles = K / 16;

#define ISSUE(t) do { \
        u32 off_ = (u32)((t) & 3) * STGB_; \
        cpa16(baseA + off_, Ap + (t) * 16); \
        cpa16(baseB + off_, Wp + (t) * 16); \
        CP_COMMIT; \
    } while (0)

    ISSUE(0); ISSUE(1); ISSUE(2);

    for (int t = 0; t < ntiles; t++) {
        CP_WAIT2;
        __syncthreads();
        if (t + 3 < ntiles) ISSUE(t + 3);
        int buf = t & 3;

        unsigned af[2][4];
        unsigned bf[8][2];
#pragma unroll
        for (int mt = 0; mt < 2; mt++)
            ldm4(af[mt], &sA[buf][aoff[mt]]);
#pragma unroll
        for (int q = 0; q < 4; q++) {
            unsigned r[4];
            ldm4(r, &sB[buf][boff[q]]);
            bf[2*q][0] = r[0]; bf[2*q][1] = r[1];
            bf[2*q+1][0] = r[2]; bf[2*q+1][1] = r[3];
        }
#pragma unroll
        for (int mt = 0; mt < 2; mt++)
#pragma unroll
            for (int nt = 0; nt < 8; nt++)
                mmah(acc[mt][nt], af[mt], bf[nt]);
    }
#undef ISSUE

    // ---- epilogue (templated; bias/gate hoisted per nt) ----
    int batch = m0 >> 10;   // M-tiles never straddle batches (1024 tokens/batch)
#pragma unroll
    for (int nt = 0; nt < 8; nt++) {
        int col = n0 + wn * 64 + nt * 8 + ((lane & 3) << 1);

        float b0 = 0.0f, b1v = 0.0f, gg0 = 0.0f, gg1 = 0.0f;
        int j = 0;
        if (MODE == 2) {
            j = col >> 1;
            if (j < FFN_) { b0 = __ldg(bias + j); b1v = __ldg(bias + FFN_ + j); }
        } else if (MODE == 3) {
            b0 = __ldg(bias + col); b1v = __ldg(bias + col + 1);
        } else if (MODE == 1) {
            b0 = __ldg(bias + col); b1v = __ldg(bias + col + 1);
            gg0 = __ldg(gate + batch * gstride + col);
            gg1 = __ldg(gate + batch * gstride + col + 1);
        } else {  // MODE 0: bounds-checked (flin)
            if (bias && col < Nout) b0 = __ldg(bias + col);
            if (bias && col + 1 < Nout) b1v = __ldg(bias + col + 1);
        }

#pragma unroll
        for (int mt = 0; mt < 2; mt++) {
            int row = m0 + wm * 32 + mt * 16 + (lane >> 2);
#pragma unroll
            for (int half = 0; half < 2; half++) {
                int m = row + half * 8;
                float a0 = acc[mt][nt][half * 2 + 0];
                float a1 = acc[mt][nt][half * 2 + 1];
                if (MODE == 2) {
                    float x1 = a0 + b0, x2 = a1 + b1v;
                    float r = x1 / (1.0f + __expf(-x1)) * x2;
                    ((u16*)Cv)[(long long)m * FFNP_ + j] = h16(r);
                } else if (MODE == 3) {
                    *reinterpret_cast<u32*>((u16*)Cv + (long long)m * ldc + col)
                        = f2h2(a0 + b0, a1 + b1v);
                } else if (MODE == 1) {
                    float* C = (float*)Cv;
                    long long idx = (long long)m * ldc + col;
                    float2 rr = *reinterpret_cast<const float2*>(res + idx);
                    float2 ov;
                    ov.x = rr.x + gg0 * (a0 + b0);
                    ov.y = rr.y + gg1 * (a1 + b1v);
                    *reinterpret_cast<float2*>(C + idx) = ov;
                } else {
                    float* C = (float*)Cv;
#pragma unroll
                    for (int e = 0; e < 2; e++) {
                        int nn = col + e;
                        if (nn < Nout)
                            C[(long long)m * ldc + nn] = ((e == 0) ? a0 + b0 : a1 + b1v);
                    }
                }
            }
        }
    }
}

// ---------------- fast weight conversion: one block per dst row ----------------
__global__ void k_wcvt_row(const float* __restrict__ src, u16* __restrict__ dst,
                           int srcK, int dstK, int srcRows, int dstRows)
{
    int r = blockIdx.x;
    int mat = r / dstRows;
    int rr = r - mat * dstRows;
    const float* s = src + ((long long)mat * srcRows + rr) * srcK;
    u16* d = dst + (long long)r * dstK;
    bool valid = rr < srcRows;
    for (int j = threadIdx.x * 2; j < dstK; j += 512) {
        float v0 = (valid && j < srcK) ? s[j] : 0.0f;
        float v1 = (valid && j + 1 < srcK) ? s[j + 1] : 0.0f;
        *reinterpret_cast<u32*>(d + j) = f2h2(v0, v1);
    }
}

__global__ void k_wcvt12_row(const float* __restrict__ src, u16* __restrict__ dst)
{
    int r = blockIdx.x;
    int dd = r / NW12_;
    int r2 = r - dd * NW12_;
    int pj = r2 >> 1;
    int hf = r2 & 1;
    u16* d = dst + (long long)r * HID_;
    if (pj >= FFN_) {
        for (int j = threadIdx.x * 2; j < HID_; j += 512)
            *reinterpret_cast<u32*>(d + j) = 0u;
        return;
    }
    const float* s = src + ((long long)dd * 2 * FFN_ + hf * FFN_ + pj) * HID_;
    for (int j = threadIdx.x * 2; j < HID_; j += 512) {
        float2 v = *reinterpret_cast<const float2*>(s + j);
        *reinterpret_cast<u32*>(d + j) = f2h2(v.x, v.y);
    }
}

// ---------------- FA2-style flash attention: register P, warp = 16 q-rows x 64 keys ----------------
constexpr int FST = 72;                   // u16 row stride
constexpr int FQH = 0;
constexpr int FQL = FQH + 128 * FST;
constexpr int FK0 = FQL + 128 * FST;      // K double buffer [2][64*FST]
constexpr int FV0 = FK0 + 2 * 64 * FST;   // V double buffer [2][64*FST]
constexpr int F_TOT = FV0 + 2 * 64 * FST;
constexpr int FLASH_SMEM = F_TOT * 2;     // 73728 bytes
constexpr int KVSTRIDE = 64 * FST;        // u16 per K/V buffer

__global__ void __launch_bounds__(256, 2)
k_flash(const float* __restrict__ gq, const u16* __restrict__ gk,
        const u16* __restrict__ gvT, u16* __restrict__ gao)
{
    extern __shared__ __align__(16) u16 su[];
    u16* sQh = su + FQH;
    u16* sQl = su + FQL;
    u16* sK  = su + FK0;
    u16* sV  = su + FV0;

    int tid = threadIdx.x;
    int lane = tid & 31;
    int warp = tid >> 5;            // 0..7, owns q rows warp*16..+15

    int bh = blockIdx.y;
    int q0 = blockIdx.x * 128;
    const float* Qg = gq + ((long long)bh * N_ + q0) * HD_;
    const u16* Kg = gk + (long long)bh * N_ * HD_;
    const u16* Vg = gvT + (long long)bh * HD_ * N_;

    // load Q (x 0.125), split fp16 hi/lo
    {
        int r = tid >> 1, c0 = (tid & 1) * 32;
#pragma unroll
        for (int i = 0; i < 8; i++) {
            float4 v = *reinterpret_cast<const float4*>(Qg + (long long)r * HD_ + c0 + i * 4);
            v.x *= 0.125f; v.y *= 0.125f; v.z *= 0.125f; v.w *= 0.125f;
            u16 h[4], l[4];
            splith(v.x, h[0], l[0]); splith(v.y, h[1], l[1]);
            splith(v.z, h[2], l[2]); splith(v.w, h[3], l[3]);
            *reinterpret_cast<uint2*>(&sQh[r * FST + c0 + i * 4]) = *reinterpret_cast<uint2*>(h);
            *reinterpret_cast<uint2*>(&sQl[r * FST + c0 + i * 4]) = *reinterpret_cast<uint2*>(l);
        }
    }

    // cp.async K/V loader mapping
    int kr = tid >> 2, kc = (tid & 3) * 16;
    u32 kdst = (u32)__cvta_generic_to_shared(sK) + (u32)(kr * FST + kc) * 2;
    u32 vdst = (u32)__cvta_generic_to_shared(sV) + (u32)(kr * FST + kc) * 2;

#define KVISSUE(cc) do { \
        u32 off_ = (u32)((cc) & 1) * (KVSTRIDE * 2); \
        const u16* ks_ = Kg + ((long long)(cc) * 64 + kr) * HD_ + kc; \
        const u16* vs_ = Vg + (long long)kr * N_ + (long long)(cc) * 64 + kc; \
        cpa16(kdst + off_, ks_); cpa16(kdst + off_ + 16, ks_ + 8); \
        cpa16(vdst + off_, vs_); cpa16(vdst + off_ + 16, vs_ + 8); \
        CP_COMMIT; \
    } while (0)

    KVISSUE(0);

    // fragment offsets
    int aoffQ = (warp * 16 + (lane & 15)) * FST + ((lane >> 4) * 8);
    int nboff[4];
#pragma unroll
    for (int g = 0; g < 4; g++)
        nboff[g] = (g * 16 + (lane & 7) + ((lane >> 4) << 3)) * FST + (((lane >> 3) & 1) * 8);

    float m_st[2] = { -1e30f, -1e30f };
    float l_st[2] = { 0.0f, 0.0f };
    float o[8][4];
#pragma unroll
    for (int nt = 0; nt < 8; nt++)
#pragma unroll
        for (int i = 0; i < 4; i++) o[nt][i] = 0.0f;

    for (int c = 0; c < 16; c++) {
        CP_WAIT0;
        __syncthreads();
        if (c < 15) KVISSUE(c + 1);
        const u16* bK = sK + (c & 1) * KVSTRIDE;
        const u16* bV = sV + (c & 1) * KVSTRIDE;

        // MMA1: S[16 q x 64 keys] = (Qh + Ql) @ K^T
        float s[8][4];
#pragma unroll
        for (int nt = 0; nt < 8; nt++)
#pragma unroll
            for (int i = 0; i < 4; i++) s[nt][i] = 0.0f;
#pragma unroll
        for (int ks = 0; ks < 4; ks++) {
            unsigned ah[4], al[4], bk[8][2];
            ldm4(ah, &sQh[aoffQ + ks * 16]);
            ldm4(al, &sQl[aoffQ + ks * 16]);
#pragma unroll
            for (int g = 0; g < 4; g++) {
                unsigned r[4];
                ldm4(r, bK + nboff[g] + ks * 16);
                bk[2*g][0] = r[0]; bk[2*g][1] = r[1];
                bk[2*g+1][0] = r[2]; bk[2*g+1][1] = r[3];
            }
#pragma unroll
            for (int nt = 0; nt < 8; nt++) {
                mmah(s[nt], ah, bk[nt]);
                mmah(s[nt], al, bk[nt]);
            }
        }

        // warp-local online softmax
#pragma unroll
        for (int h = 0; h < 2; h++) {
            float mx = m_st[h];
#pragma unroll
            for (int nt = 0; nt < 8; nt++)
                mx = fmaxf(mx, fmaxf(s[nt][2*h], s[nt][2*h+1]));
            mx = fmaxf(mx, __shfl_xor_sync(0xffffffffu, mx, 1));
            mx = fmaxf(mx, __shfl_xor_sync(0xffffffffu, mx, 2));
            float corr = __expf(m_st[h] - mx);
            float sum = 0.0f;
#pragma unroll
            for (int nt = 0; nt < 8; nt++) {
                float p0 = __expf(s[nt][2*h] - mx);
                float p1 = __expf(s[nt][2*h+1] - mx);
                sum += p0 + p1;
                s[nt][2*h] = p0; s[nt][2*h+1] = p1;
            }
            sum += __shfl_xor_sync(0xffffffffu, sum, 1);
            sum += __shfl_xor_sync(0xffffffffu, sum, 2);
            l_st[h] = l_st[h] * corr + sum;
            m_st[h] = mx;
#pragma unroll
            for (int nt = 0; nt < 8; nt++) {
                o[nt][2*h] *= corr; o[nt][2*h+1] *= corr;
            }
        }

        // pack P (register) into A fragments
        unsigned ap[4][4];
#pragma unroll
        for (int kb = 0; kb < 4; kb++) {
            ap[kb][0] = f2h2(s[2*kb][0],   s[2*kb][1]);
            ap[kb][1] = f2h2(s[2*kb][2],   s[2*kb][3]);
            ap[kb][2] = f2h2(s[2*kb+1][0], s[2*kb+1][1]);
            ap[kb][3] = f2h2(s[2*kb+1][2], s[2*kb+1][3]);
        }

        // MMA2: O[16 q x 64 d] += P @ V^T
#pragma unroll
        for (int kb = 0; kb < 4; kb++) {
            unsigned bv[8][2];
#pragma unroll
            for (int dg = 0; dg < 4; dg++) {
                unsigned r[4];
                ldm4(r, bV + nboff[dg] + kb * 16);
                bv[2*dg][0] = r[0]; bv[2*dg][1] = r[1];
                bv[2*dg+1][0] = r[2]; bv[2*dg+1][1] = r[3];
            }
#pragma unroll
            for (int nt = 0; nt < 8; nt++)
                mmah(o[nt], ap[kb], bv[nt]);
        }
    }
#undef KVISSUE

    // output: scatter into (B, N, NH, HD), scaled by 1/l
    float inv0 = 1.0f / l_st[0];
    float inv1 = 1.0f / l_st[1];
    int bb = bh >> 4, hh = bh & 15;
    int r0 = q0 + warp * 16 + (lane >> 2);
#pragma unroll
    for (int nt = 0; nt < 8; nt++) {
        int col = nt * 8 + (lane & 3) * 2;
        long long a0 = ((long long)(bb * N_ + r0) * NH_ + hh) * HD_ + col;
        long long a1 = ((long long)(bb * N_ + r0 + 8) * NH_ + hh) * HD_ + col;
        *reinterpret_cast<u32*>(gao + a0) = f2h2(o[nt][0] * inv0, o[nt][1] * inv0);
        *reinterpret_cast<u32*>(gao + a1) = f2h2(o[nt][2] * inv1, o[nt][3] * inv1);
    }
}

// ---------------- timestep embedding -> c -> silu(c) ----------------
__global__ void k_timestep(const float* __restrict__ t,
                           const float* __restrict__ t_w,
                           const float* __restrict__ t_b)
{
    int b = blockIdx.x;
    int tid = threadIdx.x;
    __shared__ float te[TDIM_];
    float tv = t[b];
    {
        int j = tid & 127;
        float f = __expf(-logf(10000.0f) * (float)j / 128.0f);
        float a = tv * f;
        te[tid] = (tid < 128) ? cosf(a) : sinf(a);
    }
    __syncthreads();
#pragma unroll
    for (int rep = 0; rep < 4; rep++) {
        int o = tid + rep * 256;
        float acc = t_b[o];
        const float* w = t_w + (long long)o * TDIM_;
        for (int j = 0; j < TDIM_; j += 4) {
            float4 wv = *reinterpret_cast<const float4*>(w + j);
            acc += te[j] * wv.x + te[j+1] * wv.y + te[j+2] * wv.z + te[j+3] * wv.w;
        }
        float sig = 1.0f / (1.0f + __expf(-acc));
        g_cs[b * HID_ + o] = acc * sig;
    }
}

// ---------------- all adaLN projections ----------------
__global__ void k_ada(const float* __restrict__ ada_w,
                      const float* __restrict__ ada_b,
                      const float* __restrict__ fada_w,
                      const float* __restrict__ fada_b)
{
    int d = blockIdx.x;
    int chunk = blockIdx.y;
    int tid = threadIdx.x;
    __shared__ float css[B_][HID_];
    for (int i = tid; i < B_ * HID_; i += 256)
        css[i >> 10][i & 1023] = g_cs[i];
    __syncthreads();

    int cnt = (d < DEPTH_) ? 6 * HID_ : 2 * HID_;
    int o = chunk * 256 + tid;
    if (o >= cnt) return;

    const float* W = (d < DEPTH_) ? ada_w + ((long long)d * 6 * HID_ + o) * HID_
                                  : fada_w + (long long)o * HID_;
    float bia = (d < DEPTH_) ? ada_b[d * 6 * HID_ + o] : fada_b[o];
    float acc[B_];
#pragma unroll
    for (int b = 0; b < B_; b++) acc[b] = bia;

    for (int j = 0; j < HID_; j += 4) {
        float4 wv = *reinterpret_cast<const float4*>(W + j);
#pragma unroll
        for (int b = 0; b < B_; b++) {
            acc[b] += css[b][j] * wv.x + css[b][j+1] * wv.y
                    + css[b][j+2] * wv.z + css[b][j+3] * wv.w;
        }
    }
#pragma unroll
    for (int b = 0; b < B_; b++) {
        if (d < DEPTH_) g_ada[((long long)(d * B_ + b)) * 6 * HID_ + o] = acc[b];
        else            g_fada[b * 2 * HID_ + o] = acc[b];
    }
}

// ---------------- patchify + bias + pos embed ----------------
__global__ void k_patch(const float* __restrict__ x,
                        const float* __restrict__ patch_w,
                        const float* __restrict__ patch_b)
{
    int tok = blockIdx.x;
    int b = tok >> 10;
    int n = tok & 1023;
    int hp = n >> 4;
    int wp = n & 15;
    int tid = threadIdx.x;
    __shared__ float xs[32];
    if (tid < 32) {
        int c = tid >> 4;
        int r = (tid >> 2) & 3;
        int q = tid & 3;
        xs[c * 16 + r * 4 + q] = x[((long long)(b * C_ + c) * H_ + hp * 4 + r) * W_ + wp * 4 + q];
    }
    __syncthreads();
    const float LOG1E4 = logf(10000.0f);
#pragma unroll
    for (int rep = 0; rep < 4; rep++) {
        int o = tid + rep * 256;
        float acc = patch_b[o];
        const float4* w4 = reinterpret_cast<const float4*>(patch_w + o * 32);
#pragma unroll
        for (int i = 0; i < 8; i++) {
            float4 wv = w4[i];
            acc += xs[i*4+0] * wv.x + xs[i*4+1] * wv.y + xs[i*4+2] * wv.z + xs[i*4+3] * wv.w;
        }
        int j = o & 255;
        int sec = o >> 8;
        float omega = __expf(-LOG1E4 * (float)j / 256.0f);
        float p = (sec < 2) ? (float)wp : (float)hp;
        float a = p * omega;
        float pos = (sec & 1) ? cosf(a) : sinf(a);
        g_h[(long long)tok * HID_ + o] = acc + pos;
    }
}

// ---------------- RMSNorm + modulate -> fp16 (warp-shuffle reduction, 1 barrier) ----------------
__global__ void k_rmsmod(const float* __restrict__ in, u16* __restrict__ out,
                         const float* __restrict__ nw,
                         const float* __restrict__ ada, int ada_stride,
                         int shift_off, int scale_off)
{
    int tok = blockIdx.x;
    int b = tok >> 10;
    int tid = threadIdx.x;
    const float* row = in + (long long)tok * HID_;
    float v[4];
    float s = 0.0f;
#pragma unroll
    for (int i = 0; i < 4; i++) { v[i] = row[tid + i * 256]; s += v[i] * v[i]; }
#pragma unroll
    for (int o = 16; o > 0; o >>= 1) s += __shfl_xor_sync(0xffffffffu, s, o);
    __shared__ float ws[8];
    if ((tid & 31) == 0) ws[tid >> 5] = s;
    __syncthreads();
    float tot = (ws[0] + ws[1]) + (ws[2] + ws[3]) + (ws[4] + ws[5]) + (ws[6] + ws[7]);
    float rs = rsqrtf(tot / (float)HID_ + EPS_);
    const float* ar = ada + (long long)b * ada_stride;
    u16* orow = out + (long long)tok * HID_;
#pragma unroll
    for (int i = 0; i < 4; i++) {
        int cidx = tid + i * 256;
        orow[cidx] = h16(v[i] * rs * nw[cidx] * (1.0f + ar[scale_off + cidx]) + ar[shift_off + cidx]);
    }
}

// ---------------- per-head qk RMSNorm + RoPE + v transpose (fp16 in) ----------------
__global__ void k_rope(const float* __restrict__ qn, const float* __restrict__ kn)
{
    int tok = blockIdx.x;
    int b = tok >> 10;
    int n = tok & 1023;
    int tid = threadIdx.x;
    int h = tid >> 4;
    int l = tid & 15;
    int d0 = l * 4;
    const u16* row = g_qkv + (long long)tok * 3 * HID_;
    uint2 qr = *reinterpret_cast<const uint2*>(row + h * HD_ + d0);
    uint2 kr = *reinterpret_cast<const uint2*>(row + HID_ + h * HD_ + d0);
    uint2 vr = *reinterpret_cast<const uint2*>(row + 2 * HID_ + h * HD_ + d0);
    float2 q01 = h2f(qr.x), q23 = h2f(qr.y);
    float2 k01 = h2f(kr.x), k23 = h2f(kr.y);
    float4 q = make_float4(q01.x, q01.y, q23.x, q23.y);
    float4 k = make_float4(k01.x, k01.y, k23.x, k23.y);

    float sq = q.x*q.x + q.y*q.y + q.z*q.z + q.w*q.w;
    float sk = k.x*k.x + k.y*k.y + k.z*k.z + k.w*k.w;
#pragma unroll
    for (int o = 1; o < 16; o <<= 1) {
        sq += __shfl_xor_sync(0xffffffffu, sq, o);
        sk += __shfl_xor_sync(0xffffffffu, sk, o);
    }
    float rq = rsqrtf(sq / (float)HD_ + EPS_);
    float rk = rsqrtf(sk / (float)HD_ + EPS_);
    q.x *= rq * qn[d0+0]; q.y *= rq * qn[d0+1]; q.z *= rq * qn[d0+2]; q.w *= rq * qn[d0+3];
    k.x *= rk * kn[d0+0]; k.y *= rk * kn[d0+1]; k.z *= rk * kn[d0+2]; k.w *= rk * kn[d0+3];

    const float LOG1E4 = logf(10000.0f);
    float hpos = (float)(n >> 4);
    float wpos = (float)(n & 15);
#pragma unroll
    for (int pr = 0; pr < 2; pr++) {
        int dp = d0 + pr * 2;
        int jj; float pos;
        if (dp < 32) { jj = dp;      pos = hpos; }
        else         { jj = dp - 32; pos = wpos; }
        float freq = __expf(-LOG1E4 * (float)jj / 32.0f);
        float ang = pos * freq;
        float c = cosf(ang), s = sinf(ang);
        float qx0 = (pr == 0) ? q.x : q.z;
        float qx1 = (pr == 0) ? q.y : q.w;
        float kx0 = (pr == 0) ? k.x : k.z;
        float kx1 = (pr == 0) ? k.y : k.w;
        float qy0 = qx0 * c - qx1 * s;
        float qy1 = qx1 * c + qx0 * s;
        float ky0 = kx0 * c - kx1 * s;
        float ky1 = kx1 * c + kx0 * s;
        if (pr == 0) { q.x = qy0; q.y = qy1; k.x = ky0; k.y = ky1; }
        else         { q.z = qy0; q.w = qy1; k.z = ky0; k.w = ky1; }
    }

    long long qbase = ((long long)(b * NH_ + h) * N_ + n) * HD_ + d0;
    *reinterpret_cast<float4*>(g_q + qbase) = q;
    uint2 kp; kp.x = f2h2(k.x, k.y); kp.y = f2h2(k.z, k.w);
    *reinterpret_cast<uint2*>(g_k + qbase) = kp;
    long long vb = (long long)(b * NH_ + h) * HD_;
    g_vT[(vb + d0 + 0) * N_ + n] = (u16)(vr.x & 0xffff);
    g_vT[(vb + d0 + 1) * N_ + n] = (u16)(vr.x >> 16);
    g_vT[(vb + d0 + 2) * N_ + n] = (u16)(vr.y & 0xffff);
    g_vT[(vb + d0 + 3) * N_ + n] = (u16)(vr.y >> 16);
}

// ---------------- unpatchify ----------------
__global__ void k_unpatch(float* __restrict__ out)
{
    int idx = blockIdx.x * 256 + threadIdx.x;
    if (idx >= B_ * C_ * H_ * W_) return;
    int ww = idx % W_;
    int tmp = idx / W_;
    int hh = tmp % H_;
    int tmp2 = tmp / H_;
    int c = tmp2 % C_;
    int b = tmp2 / C_;
    int hp = hh >> 2, p = hh & 3;
    int wp = ww >> 2, q = ww & 3;
    out[idx] = g_fin[((long long)(b * N_ + hp * WP_ + wp)) * OUT_ + p * (PW_ * C_) + q * C_ + c];
}

// ---------------- host orchestration ----------------
extern "C" void kernel_launch(void* const* d_in, const int* in_sizes, int n_in,
                              void* d_out, int out_size)
{
    const float* x       = (const float*)d_in[0];
    const float* t       = (const float*)d_in[1];
    const float* patch_w = (const float*)d_in[2];
    const float* patch_b = (const float*)d_in[3];
    const float* t_w     = (const float*)d_in[4];
    const float* t_b     = (const float*)d_in[5];
    const float* norm1_w = (const float*)d_in[6];
    const float* qkv_w   = (const float*)d_in[7];
    const float* qkv_b   = (const float*)d_in[8];
    const float* qn_w    = (const float*)d_in[9];
    const float* kn_w    = (const float*)d_in[10];
    const float* proj_w  = (const float*)d_in[11];
    const float* proj_b  = (const float*)d_in[12];
    const float* norm2_w = (const float*)d_in[13];
    const float* w12_w   = (const float*)d_in[14];
    const float* w12_b   = (const float*)d_in[15];
    const float* w3_w    = (const float*)d_in[16];
    const float* w3_b    = (const float*)d_in[17];
    const float* ada_w   = (const float*)d_in[18];
    const float* ada_b   = (const float*)d_in[19];
    const float* fnorm_w = (const float*)d_in[20];
    const float* flin_w  = (const float*)d_in[21];
    const float* flin_b  = (const float*)d_in[22];
    const float* fada_w  = (const float*)d_in[23];
    const float* fada_b  = (const float*)d_in[24];
    float* out = (float*)d_out;

    cudaFuncSetAttribute(k_flash, cudaFuncAttributeMaxDynamicSharedMemorySize, FLASH_SMEM);

    float *p_h, *p_q, *p_fin, *p_ada, *p_fada;
    u16 *p_hn, *p_qkv, *p_k, *p_vT, *p_ao, *p_ffn, *p_wq, *p_wp, *p_w12, *p_w3, *p_wf;
    cudaGetSymbolAddress((void**)&p_h,   g_h);
    cudaGetSymbolAddress((void**)&p_hn,  g_hn);
    cudaGetSymbolAddress((void**)&p_qkv, g_qkv);
    cudaGetSymbolAddress((void**)&p_q,   g_q);
    cudaGetSymbolAddress((void**)&p_k,   g_k);
    cudaGetSymbolAddress((void**)&p_vT,  g_vT);
    cudaGetSymbolAddress((void**)&p_ao,  g_ao);
    cudaGetSymbolAddress((void**)&p_ffn, g_ffn);
    cudaGetSymbolAddress((void**)&p_fin, g_fin);
    cudaGetSymbolAddress((void**)&p_ada, g_ada);
    cudaGetSymbolAddress((void**)&p_fada, g_fada);
    cudaGetSymbolAddress((void**)&p_wq,  g_wq);
    cudaGetSymbolAddress((void**)&p_wp,  g_wp);
    cudaGetSymbolAddress((void**)&p_w12, g_w12);
    cudaGetSymbolAddress((void**)&p_w3,  g_w3);
    cudaGetSymbolAddress((void**)&p_wf,  g_wf);

    auto cvt = [](const float* src, u16* dst, int srcK, int dstK,
                  int srcRows, int dstRows, int mats) {
        k_wcvt_row<<<mats * dstRows, 256>>>(src, dst, srcK, dstK, srcRows, dstRows);
    };

    // setup
    k_timestep<<<B_, 256>>>(t, t_w, t_b);
    k_ada<<<dim3(DEPTH_ + 1, 24), 256>>>(ada_w, ada_b, fada_w, fada_b);
    cvt(qkv_w, p_wq, HID_, HID_, 3 * HID_, 3 * HID_, DEPTH_);
    cvt(proj_w, p_wp, HID_, HID_, HID_, HID_, DEPTH_);
    k_wcvt12_row<<<DEPTH_ * NW12_, 256>>>(w12_w, p_w12);
    cvt(w3_w, p_w3, FFN_, FFNP_, HID_, HID_, DEPTH_);
    cvt(flin_w, p_wf, HID_, HID_, OUT_, OUTP_, 1);
    k_patch<<<T_, 256>>>(x, patch_w, patch_b);

    for (int d = 0; d < DEPTH_; d++) {
        const float* adab = p_ada + (long long)d * B_ * 6 * HID_;

        // norm1 + modulate -> fp16
        k_rmsmod<<<T_, 256>>>(p_h, p_hn, norm1_w + d * HID_, adab, 6 * HID_, 0, HID_);

        // qkv -> fp16 (MODE 3)
        {
            dim3 grid((3 * HID_) / 128, T_ / 128);
            k_gemm_h1<3><<<grid, 256>>>(p_hn, HID_, p_wq + (long long)d * 3 * HID_ * HID_, HID_,
                                        p_qkv, 3 * HID_, T_, 3 * HID_, HID_,
                                        qkv_b + d * 3 * HID_, nullptr, nullptr, 0);
        }

        // qk-norm + rope + v transpose
        k_rope<<<T_, 256>>>(qn_w + d * HD_, kn_w + d * HD_);

        // fused flash attention -> g_ao (fp16)
        k_flash<<<dim3(N_ / 128, B_ * NH_), 256, FLASH_SMEM>>>(p_q, p_k, p_vT, p_ao);

        // proj + gated residual (MODE 1)
        {
            dim3 grid(HID_ / 128, T_ / 128);
            k_gemm_h1<1><<<grid, 256>>>(p_ao, HID_, p_wp + (long long)d * HID_ * HID_, HID_,
                                        p_h, HID_, T_, HID_, HID_,
                                        proj_b + d * HID_, p_h, adab + 2 * HID_, 6 * HID_);
        }

        // norm2 + modulate -> fp16
        k_rmsmod<<<T_, 256>>>(p_h, p_hn, norm2_w + d * HID_, adab, 6 * HID_, 3 * HID_, 4 * HID_);

        // w12 GEMM with fused swiglu -> g_ffn (MODE 2)
        {
            dim3 grid(NW12_ / 128, T_ / 128);
            k_gemm_h1<2><<<grid, 256>>>(p_hn, HID_, p_w12 + (long long)d * NW12_ * HID_, HID_,
                                        p_ffn, FFNP_, T_, NW12_, HID_,
                                        w12_b + (long long)d * 2 * FFN_, nullptr, nullptr, 0);
        }

        // w3 + gated residual (MODE 1)
        {
            dim3 grid(HID_ / 128, T_ / 128);
            k_gemm_h1<1><<<grid, 256>>>(p_ffn, FFNP_, p_w3 + (long long)d * HID_ * FFNP_, FFNP_,
                                        p_h, HID_, T_, HID_, FFNP_,
                                        w3_b + d * HID_, p_h, adab + 5 * HID_, 6 * HID_);
        }
    }

    // final norm + modulate -> fp16
    k_rmsmod<<<T_, 256>>>(p_h, p_hn, fnorm_w, p_fada, 2 * HID_, 0, HID_);

    // final linear (MODE 0, bounds-checked)
    {
        dim3 grid(1, T_ / 128);
        k_gemm_h1<0><<<grid, 256>>>(p_hn, HID_, p_wf, HID_,
                                    p_fin, OUT_, T_, OUT_, HID_,
                                    flin_b, nullptr, nullptr, 0);
    }

    k_unpatch<<<(B_ * C_ * H_ * W_ + 255) / 256, 256>>>(out);
}